// round 7
// baseline (speedup 1.0000x reference)
#include <cuda_runtime.h>

#define DD     4096
#define KB     128
#define TROWS  16384

__device__ int            g_offsets[KB + 1];
__device__ unsigned short g_perm[DD];                 // CSR: j per entry
__device__ unsigned short g_pperm[KB * 4 * 16];       // padded pre-swz byte offs
__device__ float4         g_Yt[(TROWS / 4) * KB];     // [t/4][k] = y rows t..t+3

// staging stride 8: j=8t+q -> swz low3 = q ^ (t&7): conflict-free
__device__ __forceinline__ int swz(int j) { return j ^ ((j >> 3) & 7); }

__device__ __forceinline__ void fma2(unsigned long long& d,
                                     unsigned long long a, unsigned long long b) {
    asm("fma.rn.f32x2 %0, %1, %2, %0;" : "+l"(d) : "l"(a), "l"(b));
}
__device__ __forceinline__ void add2(unsigned long long& d, unsigned long long a) {
    asm("add.rn.f32x2 %0, %0, %1;" : "+l"(d) : "l"(a));
}
__device__ __forceinline__ unsigned long long pack2(float q) {
    unsigned long long r;
    asm("mov.b64 %0, {%1, %1};" : "=l"(r) : "r"(__float_as_uint(q)));
    return r;
}
__device__ __forceinline__ float lo2(unsigned long long v) {
    return __uint_as_float((unsigned)v);
}
__device__ __forceinline__ float hi2(unsigned long long v) {
    return __uint_as_float((unsigned)(v >> 32));
}

// ---------------------------------------------------------------------------
// k0: 128 blocks x 256 thr. Block b builds bin b's CSR segment + padded table.
// ---------------------------------------------------------------------------
__global__ void __launch_bounds__(256)
k0_build(const int* __restrict__ assign) {
    __shared__ unsigned char s_a[DD];
    __shared__ int s_wcnt[8], s_wlt[8];
    const int b = blockIdx.x, tid = threadIdx.x;
    const int lane = tid & 31, w = tid >> 5;

    for (int j = tid; j < DD; j += 256) s_a[j] = (unsigned char)(assign[j] & 127);
    __syncthreads();

    // warp w scans js [512w, 512w+512): count hits(==b) and lt(<b)
    int hit = 0, lt = 0;
    #pragma unroll
    for (int i = 0; i < 16; i++) {
        int a = (int)s_a[w * 512 + i * 32 + lane];
        hit += (a == b); lt += (a < b);
    }
    #pragma unroll
    for (int d = 16; d >= 1; d >>= 1) {
        hit += __shfl_xor_sync(0xffffffffu, hit, d);
        lt  += __shfl_xor_sync(0xffffffffu, lt, d);
    }
    if (lane == 0) { s_wcnt[w] = hit; s_wlt[w] = lt; }
    __syncthreads();

    int binbase = 0, warpbase = 0;
    #pragma unroll
    for (int u = 0; u < 8; u++) {
        binbase += s_wlt[u];
        if (u < w) warpbase += s_wcnt[u];
    }
    if (tid == 0) {
        g_offsets[b] = binbase;
        if (b == 0) g_offsets[KB] = DD;
    }

    // write pass: bin-relative entry index er, stable in j order
    int e = warpbase;
    #pragma unroll
    for (int i = 0; i < 16; i++) {
        int j = w * 512 + i * 32 + lane;
        bool h = ((int)s_a[j] == b);
        unsigned m = __ballot_sync(0xffffffffu, h);
        if (h) {
            int er = e + __popc(m & ((1u << lane) - 1u));
            g_perm[binbase + er] = (unsigned short)j;
            if (er < 64)
                g_pperm[(b * 4 + (er & 3)) * 16 + (er >> 2)] =
                    (unsigned short)(swz(j) << 4);
        }
        e += __popc(m);
    }
}

// ---------------------------------------------------------------------------
// K1: Y = per-bin sums. 512 thr, 2 CTAs/SM, 32 rows/CTA (8 batches of 4).
// Gather offsets live in registers (batch-invariant). Packed f32x2 adds.
// ---------------------------------------------------------------------------
#define K1_OFF_PP   65536
#define K1_OFF_PERM (K1_OFF_PP + 16384)
#define K1_OFF_OFFS (K1_OFF_PERM + 8192)
#define K1_SMEM     (K1_OFF_OFFS + 4 * (KB + 1))

__global__ void __launch_bounds__(512, 2)
k1_bins(const float* __restrict__ x) {
    extern __shared__ char smem[];
    float4*         s_x4   = (float4*)smem;                          // 64 KB
    unsigned short* s_pp   = (unsigned short*)(smem + K1_OFF_PP);    // 16 KB
    unsigned short* s_perm = (unsigned short*)(smem + K1_OFF_PERM);  // 8 KB (tail)
    int*            s_off  = (int*)(smem + K1_OFF_OFFS);

    const int tid = threadIdx.x;

    for (int i = tid; i < KB * 4 * 16 / 2; i += 512)
        ((unsigned*)s_pp)[i] = ((const unsigned*)g_pperm)[i];
    for (int i = tid; i < DD / 2; i += 512) {
        unsigned pr = ((const unsigned*)g_perm)[i];
        unsigned o0 = (unsigned)(swz((int)(pr & 0xffffu)) << 4);
        unsigned o1 = (unsigned)(swz((int)(pr >> 16)) << 4);
        ((unsigned*)s_perm)[i] = o0 | (o1 << 16);
    }
    if (tid <= KB) s_off[tid] = g_offsets[tid];

    const int bin = tid >> 2, sub = tid & 3;
    const float4* x4 = (const float4*)x;
    const int t0 = blockIdx.x * 32;

    float4 v[4][2];
    #pragma unroll
    for (int r = 0; r < 4; r++) {
        v[r][0] = x4[(size_t)(t0 + r) * 1024 + 2 * tid];
        v[r][1] = x4[(size_t)(t0 + r) * 1024 + 2 * tid + 1];
    }
    __syncthreads();

    // register-cache this thread's 16 padded offsets (batch-invariant)
    unsigned o[8];
    {
        const uint4* pp = (const uint4*)(s_pp + (bin * 4 + sub) * 16);
        uint4 pa = pp[0], pb = pp[1];
        o[0] = pa.x; o[1] = pa.y; o[2] = pa.z; o[3] = pa.w;
        o[4] = pb.x; o[5] = pb.y; o[6] = pb.z; o[7] = pb.w;
    }
    const int lo0 = s_off[bin], hi0 = s_off[bin + 1];
    const int len = hi0 - lo0;
    const int lim = len < 64 ? len : 64;
    const int cnt = (lim - sub + 3) >> 2;          // entries er==sub (mod 4), er<lim
    const int ts0 = lo0 + 64 + sub;                // CSR tail start (rarely used)

    #pragma unroll 1
    for (int b = 0; b < 8; b++) {
        const int tb = t0 + 4 * b;

        #pragma unroll
        for (int p = 0; p < 2; p++) {
            s_x4[swz(8 * tid + 4 * p + 0)] = make_float4(v[0][p].x, v[1][p].x, v[2][p].x, v[3][p].x);
            s_x4[swz(8 * tid + 4 * p + 1)] = make_float4(v[0][p].y, v[1][p].y, v[2][p].y, v[3][p].y);
            s_x4[swz(8 * tid + 4 * p + 2)] = make_float4(v[0][p].z, v[1][p].z, v[2][p].z, v[3][p].z);
            s_x4[swz(8 * tid + 4 * p + 3)] = make_float4(v[0][p].w, v[1][p].w, v[2][p].w, v[3][p].w);
        }
        __syncthreads();

        if (b < 7) {
            #pragma unroll
            for (int r = 0; r < 4; r++) {
                v[r][0] = x4[(size_t)(tb + 4 + r) * 1024 + 2 * tid];
                v[r][1] = x4[(size_t)(tb + 4 + r) * 1024 + 2 * tid + 1];
            }
        }

        // gather: 16 predicated independent LDS.128 + packed f32x2 adds
        unsigned long long accA = 0ull, accB = 0ull;   // rows 0-1, 2-3
        const char* bx = (const char*)s_x4;
        #pragma unroll
        for (int k = 0; k < 16; k++) {
            if (k < cnt) {
                unsigned off = (o[k >> 1] >> ((k & 1) * 16)) & 0xffffu;
                ulonglong2 xv = *(const ulonglong2*)(bx + off);
                add2(accA, xv.x);
                add2(accB, xv.y);
            }
        }
        for (int s2 = ts0; s2 < hi0; s2 += 4) {        // tail (len>64), ~never
            ulonglong2 xv = *(const ulonglong2*)(bx + s_perm[s2]);
            add2(accA, xv.x);
            add2(accB, xv.y);
        }

        // reduce 4 subs (adjacent lanes)
        #pragma unroll
        for (int d = 2; d >= 1; d >>= 1) {
            add2(accA, __shfl_down_sync(0xffffffffu, accA, d));
            add2(accB, __shfl_down_sync(0xffffffffu, accB, d));
        }
        if (sub == 0)
            g_Yt[(tb >> 2) * KB + bin] =
                make_float4(lo2(accA), hi2(accA), lo2(accB), hi2(accB));
        __syncthreads();
    }
}

// ---------------------------------------------------------------------------
// K2: out[t,j] = (Y[t] @ QV)[a_j] + bias[j]. 512 thr, 32 rows/CTA, 2 CTA/SM.
// Two 16-row passes share the QV smem load; qm double-buffered (5 barriers).
// ---------------------------------------------------------------------------
#define K2_OFF_Y    65536
#define K2_OFF_PART (K2_OFF_Y + 16384)
#define K2_OFF_QM   (K2_OFF_PART + 16384)
#define K2_SMEM     (K2_OFF_QM + 2 * 8192)      // 64+16+16+16 = 112 KB

__global__ void __launch_bounds__(512, 2)
k2_out(const float* __restrict__ qv, const int* __restrict__ assign,
       const float* __restrict__ bias, float* __restrict__ out) {
    extern __shared__ char smem[];
    float*  s_qv   = (float*)smem;                      // [128*128]
    float4* s_y4   = (float4*)(smem + K2_OFF_Y);        // [8 groups][128]
    float4* s_part = (float4*)(smem + K2_OFF_PART);     // [4 gg][2 cc][128]
    float4* s_qm   = (float4*)(smem + K2_OFF_QM);       // [2 bufs][4 gg][128]

    const int tid   = threadIdx.x;
    const int kout  = tid & 127;
    const int cc    = (tid >> 7) & 1;      // k'-half
    const int gpair = tid >> 8;            // group pair 0/1

    #pragma unroll
    for (int u = 0; u < 8; u++)
        ((float4*)s_qv)[u * 512 + tid] = ((const float4*)qv)[u * 512 + tid];

    const int t0 = blockIdx.x * 32;
    #pragma unroll
    for (int u = 0; u < 2; u++)
        s_y4[u * 512 + tid] = g_Yt[(t0 >> 2) * KB + u * 512 + tid];

    float4 biasr[2]; unsigned ar[2];
    #pragma unroll
    for (int s = 0; s < 2; s++) {
        int e4 = s * 512 + tid;
        biasr[s] = ((const float4*)bias)[e4];
        int4 a = ((const int4*)assign)[e4];
        ar[s] = (unsigned)(a.x & 127)
              | ((unsigned)(a.y & 127) << 8)
              | ((unsigned)(a.z & 127) << 16)
              | ((unsigned)(a.w & 127) << 24);
    }
    __syncthreads();

    float4* out4 = (float4*)out;

    #pragma unroll 1
    for (int p = 0; p < 2; p++) {
        // matvec: this thread covers groups {2gpair, 2gpair+1} of pass p,
        // k' in [cc*64, cc*64+64), output column kout
        unsigned long long a0lo = 0ull, a0hi = 0ull, a1lo = 0ull, a1hi = 0ull;
        const ulonglong2* syA = (const ulonglong2*)(s_y4 + (4 * p + 2 * gpair) * KB);
        const ulonglong2* syB = syA + KB;
        #pragma unroll
        for (int i = 0; i < 64; i++) {
            unsigned long long qd = pack2(s_qv[(cc * 64 + i) * KB + kout]);
            ulonglong2 ya = syA[cc * 64 + i];   // warp-broadcast
            ulonglong2 yb = syB[cc * 64 + i];
            fma2(a0lo, ya.x, qd); fma2(a0hi, ya.y, qd);
            fma2(a1lo, yb.x, qd); fma2(a1hi, yb.y, qd);
        }
        s_part[(2 * gpair + 0) * 256 + cc * 128 + kout] =
            make_float4(lo2(a0lo), hi2(a0lo), lo2(a0hi), hi2(a0hi));
        s_part[(2 * gpair + 1) * 256 + cc * 128 + kout] =
            make_float4(lo2(a1lo), hi2(a1lo), lo2(a1hi), hi2(a1hi));
        __syncthreads();

        {   // reduce the two k'-halves; qm double-buffered per pass
            int gg = tid >> 7;
            float4 t = s_part[gg * 256 + kout];
            float4 u = s_part[gg * 256 + 128 + kout];
            s_qm[p * 512 + gg * 128 + kout] =
                make_float4(t.x + u.x, t.y + u.y, t.z + u.z, t.w + u.w);
        }
        __syncthreads();

        // epilogue (barrier-free): 16 rows x 2 slots
        #pragma unroll
        for (int gg = 0; gg < 4; gg++) {
            const float4* qm = s_qm + p * 512 + gg * KB;
            #pragma unroll
            for (int s = 0; s < 2; s++) {
                unsigned a = ar[s];
                float4 q0 = qm[a & 255];
                float4 q1 = qm[(a >> 8)  & 255];
                float4 q2 = qm[(a >> 16) & 255];
                float4 q3 = qm[a >> 24];
                float4 bb = biasr[s];
                size_t rb = (size_t)(t0 + 16 * p + 4 * gg) * 1024 + s * 512 + tid;
                out4[rb]        = make_float4(q0.x + bb.x, q1.x + bb.y, q2.x + bb.z, q3.x + bb.w);
                out4[rb + 1024] = make_float4(q0.y + bb.x, q1.y + bb.y, q2.y + bb.z, q3.y + bb.w);
                out4[rb + 2048] = make_float4(q0.z + bb.x, q1.z + bb.y, q2.z + bb.z, q3.z + bb.w);
                out4[rb + 3072] = make_float4(q0.w + bb.x, q1.w + bb.y, q2.w + bb.z, q3.w + bb.w);
            }
        }
    }
}

extern "C" void kernel_launch(void* const* d_in, const int* in_sizes, int n_in,
                              void* d_out, int out_size) {
    const float* x      = (const float*)d_in[0];
    const float* qv     = (const float*)d_in[1];
    const int*   assign = (const int*)d_in[2];
    const float* bias   = (const float*)d_in[3];
    float*       out    = (float*)d_out;

    (void)cudaFuncSetAttribute(k1_bins,
        cudaFuncAttributeMaxDynamicSharedMemorySize, K1_SMEM);
    (void)cudaFuncSetAttribute(k2_out,
        cudaFuncAttributeMaxDynamicSharedMemorySize, K2_SMEM);

    k0_build<<<KB, 256>>>(assign);
    k1_bins<<<TROWS / 32, 512, K1_SMEM>>>(x);
    k2_out<<<TROWS / 32, 512, K2_SMEM>>>(qv, assign, bias, out);
}

// round 8
// speedup vs baseline: 1.0049x; 1.0049x over previous
#include <cuda_runtime.h>

#define DD     4096
#define KB     128
#define TROWS  16384

__device__ float4 g_Yt[(TROWS / 4) * KB];   // [t/4][k] = y rows t..t+3

// staging stride 8: j=8t+q -> swz low3 = q ^ (t&7): conflict-free
__device__ __forceinline__ int swz(int j) { return j ^ ((j >> 3) & 7); }

__device__ __forceinline__ void fma2(unsigned long long& d,
                                     unsigned long long a, unsigned long long b) {
    asm("fma.rn.f32x2 %0, %1, %2, %0;" : "+l"(d) : "l"(a), "l"(b));
}
__device__ __forceinline__ unsigned long long pack2(float q) {
    unsigned long long r;
    asm("mov.b64 %0, {%1, %1};" : "=l"(r) : "r"(__float_as_uint(q)));
    return r;
}
__device__ __forceinline__ float lo2(unsigned long long v) {
    return __uint_as_float((unsigned)v);
}
__device__ __forceinline__ float hi2(unsigned long long v) {
    return __uint_as_float((unsigned)(v >> 32));
}

// ---------------------------------------------------------------------------
// K1: Y = per-bin sums. 512 thr, 2 CTAs/SM, 32 rows/CTA (8 batches of 4 rows).
// CSR built per-CTA in a smem prologue (no separate kernel, no atomics).
// ---------------------------------------------------------------------------
#define K1_OFF_PERM 65536
#define K1_OFF_OFFS (K1_OFF_PERM + 8192)
#define K1_SMEM     (K1_OFF_OFFS + 4 * (KB + 1))

__global__ void __launch_bounds__(512, 2)
k1_bins(const float* __restrict__ x, const int* __restrict__ assign) {
    extern __shared__ char smem[];
    float4*         s_x4   = (float4*)smem;                         // 64 KB
    unsigned short* s_perm = (unsigned short*)(smem + K1_OFF_PERM); // pre-swz byte offs
    int*            s_off  = (int*)(smem + K1_OFF_OFFS);
    // prologue overlays (dead before first staging):
    unsigned char*  s_a    = (unsigned char*)smem;                  // [4096]
    unsigned short* s_cnt  = (unsigned short*)(smem + 4096);        // [128][16]
    __shared__ int  s_wsum[16];

    const int tid = threadIdx.x, lane = tid & 31, w = tid >> 5;

    // ---- prologue: per-CTA deterministic CSR of assignments -----------------
    for (int i = tid; i < 1024; i += 512) {
        int4 a = ((const int4*)assign)[i];
        uchar4 cc;
        cc.x = (unsigned char)(a.x & 127); cc.y = (unsigned char)(a.y & 127);
        cc.z = (unsigned char)(a.z & 127); cc.w = (unsigned char)(a.w & 127);
        ((uchar4*)s_a)[i] = cc;
    }
    ((unsigned*)s_cnt)[tid]       = 0;
    ((unsigned*)s_cnt)[tid + 512] = 0;
    __syncthreads();

    // counting: warp w owns js [256w, 256w+256); column w of s_cnt is private
    #pragma unroll
    for (int r = 0; r < 8; r++) {
        int a = (int)s_a[256 * w + 32 * r + lane];
        unsigned m = __match_any_sync(0xffffffffu, a);
        if ((m & ((1u << lane) - 1u)) == 0)          // group leader
            s_cnt[a * 16 + w] += (unsigned short)__popc(m);
    }
    __syncthreads();

    // exclusive scan of the 2048 (bin,warp) cells; 4 cells per thread
    int c0 = s_cnt[4 * tid + 0], c1 = s_cnt[4 * tid + 1];
    int c2 = s_cnt[4 * tid + 2], c3 = s_cnt[4 * tid + 3];
    int sum = c0 + c1 + c2 + c3;
    int v = sum;
    #pragma unroll
    for (int d = 1; d < 32; d <<= 1) {
        int n = __shfl_up_sync(0xffffffffu, v, d);
        if (lane >= d) v += n;
    }
    if (lane == 31) s_wsum[w] = v;
    __syncthreads();
    if (w == 0) {
        int t = (lane < 16) ? s_wsum[lane] : 0;
        #pragma unroll
        for (int d = 1; d < 16; d <<= 1) {
            int n = __shfl_up_sync(0xffffffffu, t, d);
            if (lane >= d) t += n;
        }
        if (lane < 16) s_wsum[lane] = t;
    }
    __syncthreads();
    int excl = v - sum + (w > 0 ? s_wsum[w - 1] : 0);
    if ((tid & 3) == 0) s_off[tid >> 2] = excl;      // cell (bin,0) boundary
    if (tid == 0)       s_off[KB] = DD;
    s_cnt[4 * tid + 0] = (unsigned short)excl;
    s_cnt[4 * tid + 1] = (unsigned short)(excl + c0);
    s_cnt[4 * tid + 2] = (unsigned short)(excl + c0 + c1);
    s_cnt[4 * tid + 3] = (unsigned short)(excl + c0 + c1 + c2);
    __syncthreads();

    // placement (warp-sequential cursors, j ascending -> deterministic)
    #pragma unroll
    for (int r = 0; r < 8; r++) {
        int j = 256 * w + 32 * r + lane;
        int a = (int)s_a[j];
        unsigned m = __match_any_sync(0xffffffffu, a);
        int rank = __popc(m & ((1u << lane) - 1u));
        int leader = __ffs(m) - 1;
        int cur = 0;
        if (lane == leader) {
            cur = s_cnt[a * 16 + w];
            s_cnt[a * 16 + w] = (unsigned short)(cur + __popc(m));
        }
        cur = __shfl_sync(0xffffffffu, cur, leader);
        s_perm[cur + rank] = (unsigned short)(swz(j) << 4);
    }
    // ---- end prologue --------------------------------------------------------

    const int bin = tid >> 2, sub = tid & 3;
    const float4* x4 = (const float4*)x;
    const int t0 = blockIdx.x * 32;

    float4 v4[4][2];
    #pragma unroll
    for (int r = 0; r < 4; r++) {
        v4[r][0] = x4[(size_t)(t0 + r) * 1024 + 2 * tid];
        v4[r][1] = x4[(size_t)(t0 + r) * 1024 + 2 * tid + 1];
    }
    __syncthreads();   // prologue data consumed; s_off/s_perm final
    const int lo = s_off[bin] + sub, hi = s_off[bin + 1];

    #pragma unroll 1
    for (int b = 0; b < 8; b++) {
        const int tb = t0 + 4 * b;

        // transposed staging: s_x4[swz(8t+q)] = {rows tb..tb+3 of feature 8t+q}
        #pragma unroll
        for (int p = 0; p < 2; p++) {
            s_x4[swz(8 * tid + 4 * p + 0)] = make_float4(v4[0][p].x, v4[1][p].x, v4[2][p].x, v4[3][p].x);
            s_x4[swz(8 * tid + 4 * p + 1)] = make_float4(v4[0][p].y, v4[1][p].y, v4[2][p].y, v4[3][p].y);
            s_x4[swz(8 * tid + 4 * p + 2)] = make_float4(v4[0][p].z, v4[1][p].z, v4[2][p].z, v4[3][p].z);
            s_x4[swz(8 * tid + 4 * p + 3)] = make_float4(v4[0][p].w, v4[1][p].w, v4[2][p].w, v4[3][p].w);
        }
        __syncthreads();

        if (b < 7) {   // prefetch next batch under the gather
            #pragma unroll
            for (int r = 0; r < 4; r++) {
                v4[r][0] = x4[(size_t)(tb + 4 + r) * 1024 + 2 * tid];
                v4[r][1] = x4[(size_t)(tb + 4 + r) * 1024 + 2 * tid + 1];
            }
        }

        // bin gather: LDS.128 = 4 rows of one feature; 4 subs per bin
        float4 acc = make_float4(0.f, 0.f, 0.f, 0.f);
        const char* bx = (const char*)s_x4;
        for (int s = lo; s < hi; s += 4) {
            float4 xv = *(const float4*)(bx + s_perm[s]);
            acc.x += xv.x; acc.y += xv.y; acc.z += xv.z; acc.w += xv.w;
        }
        #pragma unroll
        for (int d = 2; d >= 1; d >>= 1) {
            acc.x += __shfl_down_sync(0xffffffffu, acc.x, d);
            acc.y += __shfl_down_sync(0xffffffffu, acc.y, d);
            acc.z += __shfl_down_sync(0xffffffffu, acc.z, d);
            acc.w += __shfl_down_sync(0xffffffffu, acc.w, d);
        }
        if (sub == 0) g_Yt[(tb >> 2) * KB + bin] = acc;
        __syncthreads();
    }
}

// ---------------------------------------------------------------------------
// K2: out[t,j] = (Y[t] @ QV)[a_j] + bias[j]. 512 thr, 16 rows/CTA, 2 CTA/SM.
// (byte-identical to the R5/R6 version measured at 63 us)
// ---------------------------------------------------------------------------
#define K2_OFF_Y    65536
#define K2_OFF_PART (K2_OFF_Y + 8192)
#define K2_OFF_QM   (K2_OFF_PART + 32768)
#define K2_SMEM     (K2_OFF_QM + 8192)

__global__ void __launch_bounds__(512, 2)
k2_out(const float* __restrict__ qv, const int* __restrict__ assign,
       const float* __restrict__ bias, float* __restrict__ out) {
    extern __shared__ char smem[];
    float*  s_qv   = (float*)smem;
    float4* s_y4   = (float4*)(smem + K2_OFF_Y);
    float4* s_part = (float4*)(smem + K2_OFF_PART);
    float4* s_qm   = (float4*)(smem + K2_OFF_QM);

    const int tid  = threadIdx.x;
    const int kout = tid & 127, c = tid >> 7;

    #pragma unroll
    for (int u = 0; u < 8; u++)
        ((float4*)s_qv)[u * 512 + tid] = ((const float4*)qv)[u * 512 + tid];

    const int t0 = blockIdx.x * 16;
    s_y4[tid] = g_Yt[(t0 >> 2) * KB + tid];

    float4 biasr[2]; unsigned ar[2];
    #pragma unroll
    for (int s = 0; s < 2; s++) {
        int e4 = s * 512 + tid;
        biasr[s] = ((const float4*)bias)[e4];
        int4 a = ((const int4*)assign)[e4];
        ar[s] = (unsigned)(a.x & 127)
              | ((unsigned)(a.y & 127) << 8)
              | ((unsigned)(a.z & 127) << 16)
              | ((unsigned)(a.w & 127) << 24);
    }
    __syncthreads();

    unsigned long long acc[8];
    #pragma unroll
    for (int i = 0; i < 8; i++) acc[i] = 0ull;
    const ulonglong2* sy2 = (const ulonglong2*)s_y4;
    #pragma unroll
    for (int i = 0; i < 32; i++) {
        unsigned long long qd = pack2(s_qv[(c * 32 + i) * KB + kout]);
        #pragma unroll
        for (int g = 0; g < 4; g++) {
            ulonglong2 yv = sy2[g * KB + c * 32 + i];
            fma2(acc[2 * g],     yv.x, qd);
            fma2(acc[2 * g + 1], yv.y, qd);
        }
    }
    #pragma unroll
    for (int g = 0; g < 4; g++)
        s_part[g * 512 + c * 128 + kout] = make_float4(
            lo2(acc[2 * g]), hi2(acc[2 * g]),
            lo2(acc[2 * g + 1]), hi2(acc[2 * g + 1]));
    __syncthreads();

    {
        float4 t = s_part[c * 512 + kout];
        #pragma unroll
        for (int u = 1; u < 4; u++) {
            float4 p = s_part[c * 512 + u * 128 + kout];
            t.x += p.x; t.y += p.y; t.z += p.z; t.w += p.w;
        }
        s_qm[c * KB + kout] = t;
    }
    __syncthreads();

    float4* out4 = (float4*)out;
    #pragma unroll
    for (int g = 0; g < 4; g++) {
        const float4* qm = s_qm + g * KB;
        #pragma unroll
        for (int s = 0; s < 2; s++) {
            unsigned a = ar[s];
            float4 q0 = qm[a & 255];
            float4 q1 = qm[(a >> 8)  & 255];
            float4 q2 = qm[(a >> 16) & 255];
            float4 q3 = qm[a >> 24];
            float4 bb = biasr[s];
            size_t rb = (size_t)(t0 + 4 * g) * 1024 + s * 512 + tid;
            out4[rb]        = make_float4(q0.x + bb.x, q1.x + bb.y, q2.x + bb.z, q3.x + bb.w);
            out4[rb + 1024] = make_float4(q0.y + bb.x, q1.y + bb.y, q2.y + bb.z, q3.y + bb.w);
            out4[rb + 2048] = make_float4(q0.z + bb.x, q1.z + bb.y, q2.z + bb.z, q3.z + bb.w);
            out4[rb + 3072] = make_float4(q0.w + bb.x, q1.w + bb.y, q2.w + bb.z, q3.w + bb.w);
        }
    }
}

extern "C" void kernel_launch(void* const* d_in, const int* in_sizes, int n_in,
                              void* d_out, int out_size) {
    const float* x      = (const float*)d_in[0];
    const float* qv     = (const float*)d_in[1];
    const int*   assign = (const int*)d_in[2];
    const float* bias   = (const float*)d_in[3];
    float*       out    = (float*)d_out;

    (void)cudaFuncSetAttribute(k1_bins,
        cudaFuncAttributeMaxDynamicSharedMemorySize, K1_SMEM);
    (void)cudaFuncSetAttribute(k2_out,
        cudaFuncAttributeMaxDynamicSharedMemorySize, K2_SMEM);

    k1_bins<<<TROWS / 32, 512, K1_SMEM>>>(x, assign);
    k2_out<<<TROWS / 16, 512, K2_SMEM>>>(qv, assign, bias, out);
}

// round 9
// speedup vs baseline: 1.1016x; 1.0963x over previous
#include <cuda_runtime.h>

#define DD     4096
#define KB     128
#define TROWS  16384

__device__ int            g_offsets[KB + 1];
__device__ unsigned short g_perm[DD];
__device__ float4         g_Yt[(TROWS / 4) * KB];   // [t/4][k] = y rows t..t+3

// staging stride 8: j=8t+q -> swz low3 = q ^ (t&7): conflict-free
__device__ __forceinline__ int swz(int j) { return j ^ ((j >> 3) & 7); }

__device__ __forceinline__ void fma2(unsigned long long& d,
                                     unsigned long long a, unsigned long long b) {
    asm("fma.rn.f32x2 %0, %1, %2, %0;" : "+l"(d) : "l"(a), "l"(b));
}
__device__ __forceinline__ unsigned long long pack2(float q) {
    unsigned long long r;
    asm("mov.b64 %0, {%1, %1};" : "=l"(r) : "r"(__float_as_uint(q)));
    return r;
}
__device__ __forceinline__ float lo2(unsigned long long v) {
    return __uint_as_float((unsigned)v);
}
__device__ __forceinline__ float hi2(unsigned long long v) {
    return __uint_as_float((unsigned)(v >> 32));
}

// ---------------------------------------------------------------------------
// k0: 128 blocks x 32 thr (R6 version, measured). Block b: offset + CSR seg.
// ---------------------------------------------------------------------------
__global__ void k0_build(const int* __restrict__ assign) {
    const int b = blockIdx.x, lane = threadIdx.x;

    int below = 0;
    for (int i = 0; i < DD / 32; i++) {
        int a = assign[i * 32 + lane] & 127;
        below += (a < b);
    }
    #pragma unroll
    for (int d = 16; d >= 1; d >>= 1)
        below += __shfl_xor_sync(0xffffffffu, below, d);
    int base = below;

    if (lane == 0) {
        g_offsets[b] = base;
        if (b == KB - 1) g_offsets[KB] = DD;
    }
    for (int i = 0; i < DD / 32; i++) {
        int j = i * 32 + lane;
        bool hit = ((assign[j] & 127) == b);
        unsigned m = __ballot_sync(0xffffffffu, hit);
        if (hit) g_perm[base + __popc(m & ((1u << lane) - 1u))] = (unsigned short)j;
        base += __popc(m);
    }
}

// ---------------------------------------------------------------------------
// K1: Y = per-bin sums. 512 thr, 2 CTAs/SM, 16 rows/CTA (R6 version, measured)
// ---------------------------------------------------------------------------
#define K1_OFF_PERM 65536
#define K1_OFF_OFFS (K1_OFF_PERM + 8192)
#define K1_SMEM     (K1_OFF_OFFS + 4 * (KB + 1))

__global__ void __launch_bounds__(512, 2)
k1_bins(const float* __restrict__ x) {
    extern __shared__ char smem[];
    float4*         s_x4   = (float4*)smem;                         // 64 KB
    unsigned short* s_perm = (unsigned short*)(smem + K1_OFF_PERM); // pre-swz byte offs
    int*            s_off  = (int*)(smem + K1_OFF_OFFS);

    const int tid = threadIdx.x;

    for (int i = tid; i < DD / 2; i += 512) {
        unsigned pr = ((const unsigned*)g_perm)[i];
        unsigned o0 = (unsigned)(swz((int)(pr & 0xffffu)) << 4);
        unsigned o1 = (unsigned)(swz((int)(pr >> 16)) << 4);
        ((unsigned*)s_perm)[i] = o0 | (o1 << 16);
    }
    if (tid <= KB) s_off[tid] = g_offsets[tid];

    const int bin = tid >> 2, sub = tid & 3;
    const float4* x4 = (const float4*)x;
    const int t0 = blockIdx.x * 16;

    float4 v[4][2];
    #pragma unroll
    for (int r = 0; r < 4; r++) {
        v[r][0] = x4[(size_t)(t0 + r) * 1024 + 2 * tid];
        v[r][1] = x4[(size_t)(t0 + r) * 1024 + 2 * tid + 1];
    }

    __syncthreads();
    const int lo = s_off[bin] + sub, hi = s_off[bin + 1];

    #pragma unroll 1
    for (int b = 0; b < 4; b++) {
        const int tb = t0 + 4 * b;

        #pragma unroll
        for (int p = 0; p < 2; p++) {
            s_x4[swz(8 * tid + 4 * p + 0)] = make_float4(v[0][p].x, v[1][p].x, v[2][p].x, v[3][p].x);
            s_x4[swz(8 * tid + 4 * p + 1)] = make_float4(v[0][p].y, v[1][p].y, v[2][p].y, v[3][p].y);
            s_x4[swz(8 * tid + 4 * p + 2)] = make_float4(v[0][p].z, v[1][p].z, v[2][p].z, v[3][p].z);
            s_x4[swz(8 * tid + 4 * p + 3)] = make_float4(v[0][p].w, v[1][p].w, v[2][p].w, v[3][p].w);
        }
        __syncthreads();

        if (b < 3) {
            #pragma unroll
            for (int r = 0; r < 4; r++) {
                v[r][0] = x4[(size_t)(tb + 4 + r) * 1024 + 2 * tid];
                v[r][1] = x4[(size_t)(tb + 4 + r) * 1024 + 2 * tid + 1];
            }
        }

        float4 acc = make_float4(0.f, 0.f, 0.f, 0.f);
        const char* bx = (const char*)s_x4;
        for (int s = lo; s < hi; s += 4) {
            float4 xv = *(const float4*)(bx + s_perm[s]);
            acc.x += xv.x; acc.y += xv.y; acc.z += xv.z; acc.w += xv.w;
        }
        #pragma unroll
        for (int d = 2; d >= 1; d >>= 1) {
            acc.x += __shfl_down_sync(0xffffffffu, acc.x, d);
            acc.y += __shfl_down_sync(0xffffffffu, acc.y, d);
            acc.z += __shfl_down_sync(0xffffffffu, acc.z, d);
            acc.w += __shfl_down_sync(0xffffffffu, acc.w, d);
        }
        if (sub == 0) g_Yt[(tb >> 2) * KB + bin] = acc;
        __syncthreads();
    }
}

// ---------------------------------------------------------------------------
// K2 (new): 512 thr, 16 rows/CTA, 2 CTA/SM, 2 barriers.
//   thread (gsel = tid>>7, kout = tid&127): full-k' matvec -> final qm4 for
//   its row-group; write 4 interleaved replicated copies; epilogue gathers
//   via copy (lane&3) -> near-conflict-free LDS.128.
// ---------------------------------------------------------------------------
#define K2_OFF_Y    65536                       // after 64 KB QV
#define K2_OFF_QMR  (K2_OFF_Y + 8192)           // [4 groups][128*4 copies] float4
#define K2_SMEM     (K2_OFF_QMR + 4 * KB * 4 * 16)   // 64+8+32 = 104 KB

__global__ void __launch_bounds__(512, 2)
k2_out(const float* __restrict__ qv, const int* __restrict__ assign,
       const float* __restrict__ bias, float* __restrict__ out) {
    extern __shared__ char smem[];
    float*  s_qv  = (float*)smem;                     // [128*128]
    float4* s_y4  = (float4*)(smem + K2_OFF_Y);       // [4 groups][128]
    float4* s_qmr = (float4*)(smem + K2_OFF_QMR);     // [4][128*4]

    const int tid  = threadIdx.x;
    const int kout = tid & 127, gsel = tid >> 7;
    const int lane = tid & 31;

    #pragma unroll
    for (int u = 0; u < 8; u++)
        ((float4*)s_qv)[u * 512 + tid] = ((const float4*)qv)[u * 512 + tid];

    const int t0 = blockIdx.x * 16;
    s_y4[tid] = g_Yt[(t0 >> 2) * KB + tid];

    float4 biasr[2]; unsigned ar[2];
    #pragma unroll
    for (int s = 0; s < 2; s++) {
        int e4 = s * 512 + tid;
        biasr[s] = ((const float4*)bias)[e4];
        int4 a = ((const int4*)assign)[e4];
        ar[s] = (unsigned)(a.x & 127)
              | ((unsigned)(a.y & 127) << 8)
              | ((unsigned)(a.z & 127) << 16)
              | ((unsigned)(a.w & 127) << 24);
    }
    __syncthreads();

    // matvec: full k' sweep -> final qm for (group gsel, column kout)
    unsigned long long acc01 = 0ull, acc23 = 0ull;
    const ulonglong2* sy2 = (const ulonglong2*)(s_y4 + gsel * KB);
    #pragma unroll 16
    for (int i = 0; i < 128; i++) {
        unsigned long long qd = pack2(s_qv[i * KB + kout]);  // conflict-free LDS.32
        ulonglong2 yv = sy2[i];                              // warp-broadcast LDS.128
        fma2(acc01, yv.x, qd);
        fma2(acc23, yv.y, qd);
    }
    {
        float4 qm = make_float4(lo2(acc01), hi2(acc01), lo2(acc23), hi2(acc23));
        float4* dst = s_qmr + gsel * (KB * 4);
        #pragma unroll
        for (int u = 0; u < 4; u++)
            dst[kout * 4 + ((kout + u) & 3)] = qm;           // 4 replicated copies
    }
    __syncthreads();

    // epilogue: gather qm via replicated copy (lane&3); coalesced STG.128
    float4* out4 = (float4*)out;
    const int cp = lane & 3;
    #pragma unroll
    for (int g = 0; g < 4; g++) {
        const float4* qm = s_qmr + g * (KB * 4);
        #pragma unroll
        for (int s = 0; s < 2; s++) {
            unsigned a = ar[s];
            float4 q0 = qm[(a & 255) * 4 + cp];
            float4 q1 = qm[((a >> 8)  & 255) * 4 + cp];
            float4 q2 = qm[((a >> 16) & 255) * 4 + cp];
            float4 q3 = qm[(a >> 24) * 4 + cp];
            float4 bb = biasr[s];
            size_t rb = (size_t)(t0 + 4 * g) * 1024 + s * 512 + tid;
            out4[rb]        = make_float4(q0.x + bb.x, q1.x + bb.y, q2.x + bb.z, q3.x + bb.w);
            out4[rb + 1024] = make_float4(q0.y + bb.x, q1.y + bb.y, q2.y + bb.z, q3.y + bb.w);
            out4[rb + 2048] = make_float4(q0.z + bb.x, q1.z + bb.y, q2.z + bb.z, q3.z + bb.w);
            out4[rb + 3072] = make_float4(q0.w + bb.x, q1.w + bb.y, q2.w + bb.z, q3.w + bb.w);
        }
    }
}

extern "C" void kernel_launch(void* const* d_in, const int* in_sizes, int n_in,
                              void* d_out, int out_size) {
    const float* x      = (const float*)d_in[0];
    const float* qv     = (const float*)d_in[1];
    const int*   assign = (const int*)d_in[2];
    const float* bias   = (const float*)d_in[3];
    float*       out    = (float*)d_out;

    (void)cudaFuncSetAttribute(k1_bins,
        cudaFuncAttributeMaxDynamicSharedMemorySize, K1_SMEM);
    (void)cudaFuncSetAttribute(k2_out,
        cudaFuncAttributeMaxDynamicSharedMemorySize, K2_SMEM);

    k0_build<<<KB, 32>>>(assign);
    k1_bins<<<TROWS / 16, 512, K1_SMEM>>>(x);
    k2_out<<<TROWS / 16, 512, K2_SMEM>>>(qv, assign, bias, out);
}